// round 11
// baseline (speedup 1.0000x reference)
#include <cuda_runtime.h>
#include <math.h>

#define Bc 128
#define Nc 2048
#define Mc 128
#define NBLK 16            // n-blocks per batch (128 rows each)
#define OUT_STRIDE (Mc + 2*Nc)   // 4224

// scratch (static device globals — no allocation allowed)
__device__ float g_exp [Bc * Nc];           // exp(scale*cos) per (b,n)
__device__ float g_part[Bc * NBLK * Mc];    // per-block column partial sums
__device__ float g_bsum[Bc * NBLK];         // per-block partial sum of exp

// multi-value butterfly: 16 reductions (8 dots, 8 sqnorms) over 32 lanes.
// Writes exp(scale*cos) for 8 rows, returns warp-summed exp contribution
// (valid on lane 0).
__device__ __forceinline__ float butterfly_exp(
    float r[16], int lane, float scale, float* __restrict__ dst)
{
#pragma unroll
    for (int o = 16, nv = 16; o >= 2; o >>= 1, nv >>= 1) {
        const int half = nv >> 1;
#pragma unroll
        for (int j = 0; j < half; j++) {
            float send = (lane & o) ? r[j] : r[j + half];
            float recv = __shfl_xor_sync(0xFFFFFFFFu, send, o);
            r[j] = ((lane & o) ? r[j + half] : r[j]) + recv;
        }
    }
    r[0] += __shfl_xor_sync(0xFFFFFFFFu, r[0], 1);
    // lanes 2i,2i+1 (i<8) hold dot_i ; lanes 16+2i hold sq_i
    float other = __shfl_xor_sync(0xFFFFFFFFu, r[0], 16);

    float ex = 0.f;
    if ((lane < 16) && !(lane & 1)) {
        int i = lane >> 1;
        ex = __expf(scale * r[0] * rsqrtf(fmaxf(other, 1e-16f)));
        dst[i] = ex;
    }
    ex += __shfl_xor_sync(0xFFFFFFFFu, ex, 2);
    ex += __shfl_xor_sync(0xFFFFFFFFu, ex, 4);
    ex += __shfl_xor_sync(0xFFFFFFFFu, ex, 8);
    return ex;
}

// ---------------------------------------------------------------------------
// Pass 1: lean streaming sweep (no wprev/gamma work here). 256 threads,
// NBLK=16, 16 rows/warp in 2 pipelined batches of 8.
// __launch_bounds__(256, 6): cap regs ~42 -> 6 CTAs/SM for more in-flight
// loads (streaming kernel at 66% of BW ceiling; occupancy is the lever).
// ---------------------------------------------------------------------------
__global__ void __launch_bounds__(256, 6) ntm_pass1(
    const float* __restrict__ mem, const float* __restrict__ k,
    const float* __restrict__ beta)
{
    const int b    = blockIdx.y;
    const int blk  = blockIdx.x;
    const int tid  = threadIdx.x;
    const int warp = tid >> 5;
    const int lane = tid & 31;

    // k row (with eps), 4 elements per lane
    float4 kv = ((const float4*)(k + b * Mc))[lane];
    kv.x += 1e-6f; kv.y += 1e-6f; kv.z += 1e-6f; kv.w += 1e-6f;

    // per-warp nk and scale (redundant across warps, no barrier)
    float kk = kv.x*kv.x + kv.y*kv.y + kv.z*kv.z + kv.w*kv.w;
#pragma unroll
    for (int off = 16; off; off >>= 1)
        kk += __shfl_xor_sync(0xFFFFFFFFu, kk, off);
    const float scale = beta[b] * rsqrtf(fmaxf(kk, 1e-16f));

    const int n0 = blk * 128 + warp * 16;
    const float4* mp = (const float4*)(mem + ((size_t)b * Nc + n0) * Mc);

    // batch 1 loads (rows 0..7), MLP=8
    float4 v[8];
#pragma unroll
    for (int i = 0; i < 8; i++) v[i] = mp[i * 32 + lane];

    float cs0 = 0.f, cs1 = 0.f, cs2 = 0.f, cs3 = 0.f;
    float r1[16];
#pragma unroll
    for (int i = 0; i < 8; i++) {
        float4 t = v[i];
        cs0 += t.x; cs1 += t.y; cs2 += t.z; cs3 += t.w;
        r1[i]     = t.x*kv.x + t.y*kv.y + t.z*kv.z + t.w*kv.w;
        r1[i + 8] = t.x*t.x  + t.y*t.y  + t.z*t.z  + t.w*t.w;
    }

    // batch 2 loads (rows 8..15) in flight while batch-1 butterfly runs
    float4 w[8];
#pragma unroll
    for (int i = 0; i < 8; i++) w[i] = mp[(8 + i) * 32 + lane];

    float ex = butterfly_exp(r1, lane, scale, g_exp + b * Nc + n0);

    float r2[16];
#pragma unroll
    for (int i = 0; i < 8; i++) {
        float4 t = w[i];
        cs0 += t.x; cs1 += t.y; cs2 += t.z; cs3 += t.w;
        r2[i]     = t.x*kv.x + t.y*kv.y + t.z*kv.z + t.w*kv.w;
        r2[i + 8] = t.x*t.x  + t.y*t.y  + t.z*t.z  + t.w*t.w;
    }
    ex += butterfly_exp(r2, lane, scale, g_exp + b * Nc + n0 + 8);

    __shared__ float s_cs[8][Mc];
    __shared__ float s_exw[8];
    {
        int m = lane * 4;
        s_cs[warp][m + 0] = cs0;
        s_cs[warp][m + 1] = cs1;
        s_cs[warp][m + 2] = cs2;
        s_cs[warp][m + 3] = cs3;
        if (lane == 0) s_exw[warp] = ex;
    }
    __syncthreads();

    if (tid < Mc) {
        float s = 0.f;
#pragma unroll
        for (int wi = 0; wi < 8; wi++) s += s_cs[wi][tid];
        g_part[((size_t)b * NBLK + blk) * Mc + tid] = s;
    }
    if (tid == 0) {
        float se = 0.f;
#pragma unroll
        for (int wi = 0; wi < 8; wi++) se += s_exw[wi];
        g_bsum[b * NBLK + blk] = se;
    }
}

// ---------------------------------------------------------------------------
// Pass 2 (R8 config — best measured 5.7us): one block (512 thr) per batch.
// pow computed on the wprev values already loaded for w_g; one smem reduce.
// ---------------------------------------------------------------------------
__global__ void __launch_bounds__(512) ntm_pass2(
    const float* __restrict__ gt,    const float* __restrict__ wprev,
    const float* __restrict__ gamma, const float* __restrict__ e,
    const float* __restrict__ a,     float* __restrict__ out)
{
    const int b    = blockIdx.x;
    const int tid  = threadIdx.x;
    const int warp = tid >> 5;
    const int lane = tid & 31;

    // ---- prefetch all elementwise data ----
    const float4 ex = ((const float4*)(g_exp  + b * Nc))[tid];
    const float4 wp = ((const float4*)(wprev + b * Nc))[tid];
    const float  gv  = gt[b];
    const float  gam = gamma[b];

    float evv = 0.f, avv = 0.f, Sm = 0.f;
    if (tid < Mc) {
        evv = e[b * Mc + tid];
        avv = a[b * Mc + tid];
#pragma unroll
        for (int j = 0; j < NBLK; j++)
            Sm += g_part[((size_t)b * NBLK + j) * Mc + tid];
    }

    // ---- pow on already-loaded wprev ----
    float pw = __powf(wp.x, gam) + __powf(wp.y, gam)
             + __powf(wp.z, gam) + __powf(wp.w, gam);
#pragma unroll
    for (int off = 16; off; off >>= 1)
        pw += __shfl_xor_sync(0xFFFFFFFFu, pw, off);

    __shared__ float s_pw[16];
    __shared__ float s_inv, s_sB;
    if (lane == 0) s_pw[warp] = pw;
    __syncthreads();

    if (warp == 0) {
        float p2 = (lane < 16) ? s_pw[lane] : 0.f;
        float es = (lane < NBLK) ? g_bsum[b * NBLK + lane] : 0.f;
#pragma unroll
        for (int off = 8; off; off >>= 1) {
            p2 += __shfl_xor_sync(0xFFFFFFFFu, p2, off);
            es += __shfl_xor_sync(0xFFFFFFFFu, es, off);
        }
        if (lane == 0) { s_inv = 1.f / es; s_sB = p2 + 1e-6f; }
    }
    __syncthreads();

    const float inv = s_inv;
    const float sB  = s_sB;
    const float og  = 1.f - gv;
    float* ob = out + (size_t)b * OUT_STRIDE;

    ((float4*)(ob + Mc))[tid] = make_float4(sB, sB, sB, sB);
    float4 wg;
    wg.x = gv * ex.x * inv + og * wp.x;
    wg.y = gv * ex.y * inv + og * wp.y;
    wg.z = gv * ex.z * inv + og * wp.z;
    wg.w = gv * ex.w * inv + og * wp.w;
    ((float4*)(ob + Mc + Nc))[tid] = wg;

    if (tid < Mc) {
        // r_t = sB * ((1 - sB*e) * colsum + N * sB * a)
        ob[tid] = sB * ((1.f - sB * evv) * Sm + (float)Nc * sB * avv);
    }
}

extern "C" void kernel_launch(void* const* d_in, const int* in_sizes, int n_in,
                              void* d_out, int out_size)
{
    const float* mem   = (const float*)d_in[0];
    const float* k     = (const float*)d_in[1];
    const float* beta  = (const float*)d_in[2];
    const float* gt    = (const float*)d_in[3];
    const float* wprev = (const float*)d_in[4];
    // d_in[5] = s_t (unused by the reference's live outputs)
    const float* gamma = (const float*)d_in[6];
    const float* e     = (const float*)d_in[7];
    const float* a     = (const float*)d_in[8];
    float* out = (float*)d_out;

    ntm_pass1<<<dim3(NBLK, Bc), 256>>>(mem, k, beta);
    ntm_pass2<<<Bc, 512>>>(gt, wprev, gamma, e, a, out);
}

// round 12
// speedup vs baseline: 1.2614x; 1.2614x over previous
#include <cuda_runtime.h>
#include <math.h>

#define Bc 128
#define Nc 2048
#define Mc 128
#define NBLK 16            // n-blocks per batch (128 rows each)
#define OUT_STRIDE (Mc + 2*Nc)   // 4224

// scratch (static device globals — no allocation allowed)
__device__ float g_exp [Bc * Nc];           // exp(scale*cos) per (b,n)
__device__ float g_part[Bc * NBLK * Mc];    // per-block column partial sums
__device__ float g_bsum[Bc * NBLK];         // per-block partial sum of exp
__device__ float g_bpow[Bc * NBLK];         // per-block partial sum of wprev^gamma

// multi-value butterfly: 16 reductions (8 dots, 8 sqnorms) over 32 lanes.
// Writes exp(scale*cos) for 8 rows, returns warp-summed exp contribution
// (valid on lane 0).
__device__ __forceinline__ float butterfly_exp(
    float r[16], int lane, float scale, float* __restrict__ dst)
{
#pragma unroll
    for (int o = 16, nv = 16; o >= 2; o >>= 1, nv >>= 1) {
        const int half = nv >> 1;
#pragma unroll
        for (int j = 0; j < half; j++) {
            float send = (lane & o) ? r[j] : r[j + half];
            float recv = __shfl_xor_sync(0xFFFFFFFFu, send, o);
            r[j] = ((lane & o) ? r[j + half] : r[j]) + recv;
        }
    }
    r[0] += __shfl_xor_sync(0xFFFFFFFFu, r[0], 1);
    // lanes 2i,2i+1 (i<8) hold dot_i ; lanes 16+2i hold sq_i
    float other = __shfl_xor_sync(0xFFFFFFFFu, r[0], 16);

    float ex = 0.f;
    if ((lane < 16) && !(lane & 1)) {
        int i = lane >> 1;
        ex = __expf(scale * r[0] * rsqrtf(fmaxf(other, 1e-16f)));
        dst[i] = ex;
    }
    ex += __shfl_xor_sync(0xFFFFFFFFu, ex, 2);
    ex += __shfl_xor_sync(0xFFFFFFFFu, ex, 4);
    ex += __shfl_xor_sync(0xFFFFFFFFu, ex, 8);
    return ex;
}

// ---------------------------------------------------------------------------
// Pass 1 (R9 config, software-pipelined loads): 256 threads, NBLK=16,
// 16 rows/warp rolled through a single 8-deep float4 buffer (refill row 8+i
// right after consuming row i) — sustains MLP=8 with half the load regs.
// NO launch-bounds occupancy cap (forcing it spills the hot loop: R7, R11).
// ---------------------------------------------------------------------------
__global__ void __launch_bounds__(256) ntm_pass1(
    const float* __restrict__ mem,   const float* __restrict__ k,
    const float* __restrict__ beta,  const float* __restrict__ wprev,
    const float* __restrict__ gamma)
{
    const int b    = blockIdx.y;
    const int blk  = blockIdx.x;
    const int tid  = threadIdx.x;
    const int warp = tid >> 5;
    const int lane = tid & 31;

    // k row (with eps), 4 elements per lane
    float4 kv = ((const float4*)(k + b * Mc))[lane];
    kv.x += 1e-6f; kv.y += 1e-6f; kv.z += 1e-6f; kv.w += 1e-6f;

    // per-warp nk and scale (redundant across warps, no barrier)
    float kk = kv.x*kv.x + kv.y*kv.y + kv.z*kv.z + kv.w*kv.w;
#pragma unroll
    for (int off = 16; off; off >>= 1)
        kk += __shfl_xor_sync(0xFFFFFFFFu, kk, off);
    const float scale = beta[b] * rsqrtf(fmaxf(kk, 1e-16f));

    const int n0 = blk * 128 + warp * 16;
    const float4* mp = (const float4*)(mem + ((size_t)b * Nc + n0) * Mc);

    // prime the 8-deep rolling buffer with rows 0..7 (MLP=8)
    float4 cur[8];
#pragma unroll
    for (int i = 0; i < 8; i++) cur[i] = mp[i * 32 + lane];

    float cs0 = 0.f, cs1 = 0.f, cs2 = 0.f, cs3 = 0.f;

    // consume row i, immediately refill slot with row 8+i
    float r1[16];
#pragma unroll
    for (int i = 0; i < 8; i++) {
        float4 t = cur[i];
        cur[i] = mp[(8 + i) * 32 + lane];          // refill keeps 8 in flight
        cs0 += t.x; cs1 += t.y; cs2 += t.z; cs3 += t.w;
        r1[i]     = t.x*kv.x + t.y*kv.y + t.z*kv.z + t.w*kv.w;
        r1[i + 8] = t.x*t.x  + t.y*t.y  + t.z*t.z  + t.w*t.w;
    }

    float ex = butterfly_exp(r1, lane, scale, g_exp + b * Nc + n0);

    float r2[16];
#pragma unroll
    for (int i = 0; i < 8; i++) {
        float4 t = cur[i];
        cs0 += t.x; cs1 += t.y; cs2 += t.z; cs3 += t.w;
        r2[i]     = t.x*kv.x + t.y*kv.y + t.z*kv.z + t.w*kv.w;
        r2[i + 8] = t.x*t.x  + t.y*t.y  + t.z*t.z  + t.w*t.w;
    }
    ex += butterfly_exp(r2, lane, scale, g_exp + b * Nc + n0 + 8);

    // wprev^gamma: 128 rows per block -> threads 0..127 load one row each
    float pw = 0.f;
    if (tid < 128)
        pw = __powf(wprev[b * Nc + blk * 128 + tid], gamma[b]);
#pragma unroll
    for (int off = 16; off; off >>= 1)
        pw += __shfl_xor_sync(0xFFFFFFFFu, pw, off);

    __shared__ float s_cs[8][Mc];
    __shared__ float s_exw[8];
    __shared__ float s_pww[8];
    {
        int m = lane * 4;
        s_cs[warp][m + 0] = cs0;
        s_cs[warp][m + 1] = cs1;
        s_cs[warp][m + 2] = cs2;
        s_cs[warp][m + 3] = cs3;
        if (lane == 0) { s_exw[warp] = ex; s_pww[warp] = pw; }
    }
    __syncthreads();

    if (tid < Mc) {
        float s = 0.f;
#pragma unroll
        for (int wi = 0; wi < 8; wi++) s += s_cs[wi][tid];
        g_part[((size_t)b * NBLK + blk) * Mc + tid] = s;
    }
    if (tid == 0) {
        float se = 0.f, sp = 0.f;
#pragma unroll
        for (int wi = 0; wi < 8; wi++) { se += s_exw[wi]; sp += s_pww[wi]; }
        g_bsum[b * NBLK + blk] = se;
        g_bpow[b * NBLK + blk] = sp;
    }
}

// ---------------------------------------------------------------------------
// Pass 2 (R9 config): one block (512 thr) per batch — barrier-free, warp-
// redundant 16-partial butterfly reduce, all elementwise loads prefetched.
// ---------------------------------------------------------------------------
__global__ void __launch_bounds__(512) ntm_pass2(
    const float* __restrict__ gt,   const float* __restrict__ wprev,
    const float* __restrict__ e,    const float* __restrict__ a,
    float* __restrict__ out)
{
    const int b    = blockIdx.x;
    const int tid  = threadIdx.x;
    const int lane = tid & 31;

    // ---- prefetch all elementwise data (independent of the reduce) ----
    const float4 ex = ((const float4*)(g_exp  + b * Nc))[tid];
    const float4 wp = ((const float4*)(wprev + b * Nc))[tid];
    const float  gv = gt[b];

    float evv = 0.f, avv = 0.f, Sm = 0.f;
    if (tid < Mc) {
        evv = e[b * Mc + tid];
        avv = a[b * Mc + tid];
#pragma unroll
        for (int j = 0; j < NBLK; j++)
            Sm += g_part[((size_t)b * NBLK + j) * Mc + tid];
    }

    // ---- warp-redundant scalar reduce (no barrier, no smem) ----
    float es = g_bsum[b * NBLK + (lane & 15)];
    float pw = g_bpow[b * NBLK + (lane & 15)];
#pragma unroll
    for (int off = 8; off; off >>= 1) {
        es += __shfl_xor_sync(0xFFFFFFFFu, es, off);
        pw += __shfl_xor_sync(0xFFFFFFFFu, pw, off);
    }
    const float inv = 1.f / es;
    const float sB  = pw + 1e-6f;
    const float og  = 1.f - gv;
    float* ob = out + (size_t)b * OUT_STRIDE;

    ((float4*)(ob + Mc))[tid] = make_float4(sB, sB, sB, sB);
    float4 wg;
    wg.x = gv * ex.x * inv + og * wp.x;
    wg.y = gv * ex.y * inv + og * wp.y;
    wg.z = gv * ex.z * inv + og * wp.z;
    wg.w = gv * ex.w * inv + og * wp.w;
    ((float4*)(ob + Mc + Nc))[tid] = wg;

    if (tid < Mc) {
        // r_t = sB * ((1 - sB*e) * colsum + N * sB * a)
        ob[tid] = sB * ((1.f - sB * evv) * Sm + (float)Nc * sB * avv);
    }
}

extern "C" void kernel_launch(void* const* d_in, const int* in_sizes, int n_in,
                              void* d_out, int out_size)
{
    const float* mem   = (const float*)d_in[0];
    const float* k     = (const float*)d_in[1];
    const float* beta  = (const float*)d_in[2];
    const float* gt    = (const float*)d_in[3];
    const float* wprev = (const float*)d_in[4];
    // d_in[5] = s_t (unused by the reference's live outputs)
    const float* gamma = (const float*)d_in[6];
    const float* e     = (const float*)d_in[7];
    const float* a     = (const float*)d_in[8];
    float* out = (float*)d_out;

    ntm_pass1<<<dim3(NBLK, Bc), 256>>>(mem, k, beta, wprev, gamma);
    ntm_pass2<<<Bc, 512>>>(gt, wprev, e, a, out);
}

// round 13
// speedup vs baseline: 1.2823x; 1.0165x over previous
#include <cuda_runtime.h>
#include <math.h>

#define Bc 128
#define Nc 2048
#define Mc 128
#define NBLK 16            // n-blocks per batch (128 rows each)
#define OUT_STRIDE (Mc + 2*Nc)   // 4224

// scratch (static device globals — no allocation allowed)
__device__ float g_exp [Bc * Nc];           // exp(scale*cos) per (b,n)
__device__ float g_part[Bc * NBLK * Mc];    // per-block column partial sums
__device__ float g_bsum[Bc * NBLK];         // per-block partial sum of exp
__device__ float g_bpow[Bc * NBLK];         // per-block partial sum of wprev^gamma

// multi-value butterfly: 16 reductions (8 dots, 8 sqnorms) over 32 lanes.
__device__ __forceinline__ float butterfly_exp(
    float r[16], int lane, float scale, float* __restrict__ dst)
{
#pragma unroll
    for (int o = 16, nv = 16; o >= 2; o >>= 1, nv >>= 1) {
        const int half = nv >> 1;
#pragma unroll
        for (int j = 0; j < half; j++) {
            float send = (lane & o) ? r[j] : r[j + half];
            float recv = __shfl_xor_sync(0xFFFFFFFFu, send, o);
            r[j] = ((lane & o) ? r[j + half] : r[j]) + recv;
        }
    }
    r[0] += __shfl_xor_sync(0xFFFFFFFFu, r[0], 1);
    // lanes 2i,2i+1 (i<8) hold dot_i ; lanes 16+2i hold sq_i
    float other = __shfl_xor_sync(0xFFFFFFFFu, r[0], 16);

    float ex = 0.f;
    if ((lane < 16) && !(lane & 1)) {
        int i = lane >> 1;
        ex = __expf(scale * r[0] * rsqrtf(fmaxf(other, 1e-16f)));
        dst[i] = ex;
    }
    ex += __shfl_xor_sync(0xFFFFFFFFu, ex, 2);
    ex += __shfl_xor_sync(0xFFFFFFFFu, ex, 4);
    ex += __shfl_xor_sync(0xFFFFFFFFu, ex, 8);
    return ex;
}

// ---------------------------------------------------------------------------
// Pass 1 (proven best config): 256 threads, NBLK=16, 16 rows/warp through an
// 8-deep rolling buffer. __ldcs on memory (read-once stream; keep L2 for the
// scratch pass2 re-reads). NO occupancy caps (R7/R11: forcing them spills).
// ---------------------------------------------------------------------------
__global__ void __launch_bounds__(256) ntm_pass1(
    const float* __restrict__ mem,   const float* __restrict__ k,
    const float* __restrict__ beta,  const float* __restrict__ wprev,
    const float* __restrict__ gamma)
{
    const int b    = blockIdx.y;
    const int blk  = blockIdx.x;
    const int tid  = threadIdx.x;
    const int warp = tid >> 5;
    const int lane = tid & 31;

    // k row (with eps), 4 elements per lane
    float4 kv = ((const float4*)(k + b * Mc))[lane];
    kv.x += 1e-6f; kv.y += 1e-6f; kv.z += 1e-6f; kv.w += 1e-6f;

    // per-warp nk and scale (redundant across warps, no barrier)
    float kk = kv.x*kv.x + kv.y*kv.y + kv.z*kv.z + kv.w*kv.w;
#pragma unroll
    for (int off = 16; off; off >>= 1)
        kk += __shfl_xor_sync(0xFFFFFFFFu, kk, off);
    const float scale = beta[b] * rsqrtf(fmaxf(kk, 1e-16f));

    const int n0 = blk * 128 + warp * 16;
    const float4* mp = (const float4*)(mem + ((size_t)b * Nc + n0) * Mc);

    // prime the 8-deep rolling buffer with rows 0..7 (MLP=8)
    float4 cur[8];
#pragma unroll
    for (int i = 0; i < 8; i++) cur[i] = __ldcs(mp + i * 32 + lane);

    float cs0 = 0.f, cs1 = 0.f, cs2 = 0.f, cs3 = 0.f;

    // consume row i, immediately refill slot with row 8+i
    float r1[16];
#pragma unroll
    for (int i = 0; i < 8; i++) {
        float4 t = cur[i];
        cur[i] = __ldcs(mp + (8 + i) * 32 + lane);   // refill keeps 8 in flight
        cs0 += t.x; cs1 += t.y; cs2 += t.z; cs3 += t.w;
        r1[i]     = t.x*kv.x + t.y*kv.y + t.z*kv.z + t.w*kv.w;
        r1[i + 8] = t.x*t.x  + t.y*t.y  + t.z*t.z  + t.w*t.w;
    }

    float ex = butterfly_exp(r1, lane, scale, g_exp + b * Nc + n0);

    float r2[16];
#pragma unroll
    for (int i = 0; i < 8; i++) {
        float4 t = cur[i];
        cs0 += t.x; cs1 += t.y; cs2 += t.z; cs3 += t.w;
        r2[i]     = t.x*kv.x + t.y*kv.y + t.z*kv.z + t.w*kv.w;
        r2[i + 8] = t.x*t.x  + t.y*t.y  + t.z*t.z  + t.w*t.w;
    }
    ex += butterfly_exp(r2, lane, scale, g_exp + b * Nc + n0 + 8);

    // wprev^gamma: 128 rows per block -> threads 0..127 load one row each
    float pw = 0.f;
    if (tid < 128)
        pw = __powf(wprev[b * Nc + blk * 128 + tid], gamma[b]);
#pragma unroll
    for (int off = 16; off; off >>= 1)
        pw += __shfl_xor_sync(0xFFFFFFFFu, pw, off);

    __shared__ float s_cs[8][Mc];
    __shared__ float s_exw[8];
    __shared__ float s_pww[8];
    {
        int m = lane * 4;
        s_cs[warp][m + 0] = cs0;
        s_cs[warp][m + 1] = cs1;
        s_cs[warp][m + 2] = cs2;
        s_cs[warp][m + 3] = cs3;
        if (lane == 0) { s_exw[warp] = ex; s_pww[warp] = pw; }
    }
    __syncthreads();

    if (tid < Mc) {
        float s = 0.f;
#pragma unroll
        for (int wi = 0; wi < 8; wi++) s += s_cs[wi][tid];
        g_part[((size_t)b * NBLK + blk) * Mc + tid] = s;
    }
    if (tid == 0) {
        float se = 0.f, sp = 0.f;
#pragma unroll
        for (int wi = 0; wi < 8; wi++) { se += s_exw[wi]; sp += s_pww[wi]; }
        g_bsum[b * NBLK + blk] = se;
        g_bpow[b * NBLK + blk] = sp;
    }
}

// ---------------------------------------------------------------------------
// Pass 2: grid (2, B) x 512 = 4096 warps. Warps 0-7: w_g (2 loads + store);
// warps 8-15: w_t (pure broadcast store, no loads); split 0 / tid<128: r_t.
// Barrier-free warp-redundant scalar reduce.
// ---------------------------------------------------------------------------
__global__ void __launch_bounds__(512) ntm_pass2(
    const float* __restrict__ gt,   const float* __restrict__ wprev,
    const float* __restrict__ e,    const float* __restrict__ a,
    float* __restrict__ out)
{
    const int b    = blockIdx.y;
    const int s    = blockIdx.x;          // 0 or 1 (N-half)
    const int tid  = threadIdx.x;
    const int lane = tid & 31;
    const int n4   = s * 256 + (tid & 255);   // float4 index into [Nc]

    const float gv = gt[b];

    // ---- prefetch (only the threads that need them issue loads) ----
    float4 ex4, wp4;
    if (tid < 256) {
        ex4 = ((const float4*)(g_exp  + b * Nc))[n4];
        wp4 = ((const float4*)(wprev + b * Nc))[n4];
    }
    float evv = 0.f, avv = 0.f, Sm = 0.f;
    if (s == 0 && tid < Mc) {
        evv = e[b * Mc + tid];
        avv = a[b * Mc + tid];
#pragma unroll
        for (int j = 0; j < NBLK; j++)
            Sm += g_part[((size_t)b * NBLK + j) * Mc + tid];
    }

    // ---- warp-redundant scalar reduce (no barrier, no smem) ----
    float es = g_bsum[b * NBLK + (lane & 15)];
    float pw = g_bpow[b * NBLK + (lane & 15)];
#pragma unroll
    for (int off = 8; off; off >>= 1) {
        es += __shfl_xor_sync(0xFFFFFFFFu, es, off);
        pw += __shfl_xor_sync(0xFFFFFFFFu, pw, off);
    }
    const float inv = 1.f / es;
    const float sB  = pw + 1e-6f;
    const float og  = 1.f - gv;
    float* ob = out + (size_t)b * OUT_STRIDE;

    if (tid < 256) {
        // w_g half
        float4 wg;
        wg.x = gv * ex4.x * inv + og * wp4.x;
        wg.y = gv * ex4.y * inv + og * wp4.y;
        wg.z = gv * ex4.z * inv + og * wp4.z;
        wg.w = gv * ex4.w * inv + og * wp4.w;
        ((float4*)(ob + Mc + Nc))[n4] = wg;
    } else {
        // w_t half: pure broadcast store
        ((float4*)(ob + Mc))[n4] = make_float4(sB, sB, sB, sB);
    }

    if (s == 0 && tid < Mc) {
        // r_t = sB * ((1 - sB*e) * colsum + N * sB * a)
        ob[tid] = sB * ((1.f - sB * evv) * Sm + (float)Nc * sB * avv);
    }
}

extern "C" void kernel_launch(void* const* d_in, const int* in_sizes, int n_in,
                              void* d_out, int out_size)
{
    const float* mem   = (const float*)d_in[0];
    const float* k     = (const float*)d_in[1];
    const float* beta  = (const float*)d_in[2];
    const float* gt    = (const float*)d_in[3];
    const float* wprev = (const float*)d_in[4];
    // d_in[5] = s_t (unused by the reference's live outputs)
    const float* gamma = (const float*)d_in[6];
    const float* e     = (const float*)d_in[7];
    const float* a     = (const float*)d_in[8];
    float* out = (float*)d_out;

    ntm_pass1<<<dim3(NBLK, Bc), 256>>>(mem, k, beta, wprev, gamma);
    ntm_pass2<<<dim3(2, Bc), 512>>>(gt, wprev, e, a, out);
}